// round 8
// baseline (speedup 1.0000x reference)
#include <cuda_runtime.h>
#include <stdint.h>

// DiceFromLabelsLoss: joint-histogram, single fused kernel.
// 256-thread blocks x 3/SM -> 85-reg budget so the depth-8 LDG.128 register
// pipeline fits (512x2 capped at 64 regs and ptxas collapsed the batch).
// Private u8 counters [NKEY][256] (conflict-free, no atomics in hot loop).
// dp4a byte-sum epilogue -> integer atomicAdd into global joint histogram
// (exact). Last block (ticket) finalizes + resets. Finalize phases are
// STRIDED loops (R7 bug: 1:1 thread map left J[256..399] uninitialized).

#define NBATCH  4
#define NCLS    10
#define NKEY    (NCLS * NCLS)                 // 100
#define THREADS 256
#define CHUNKS_PER_BATCH 111
#define NBLK    (NBATCH * CHUNKS_PER_BATCH)   // 444 = 3 blocks x 148 SMs
#define CNT_BYTES (NKEY * THREADS)            // 25600 B

__device__ unsigned int g_joint[NBATCH * NKEY];  // zero-init; reset by last block
__device__ unsigned int g_done;                  // ticket; reset by last block

__device__ __forceinline__ void bump(unsigned char* cnt, int4 p, int4 t, int tid)
{
    cnt[(p.x * NCLS + t.x) * THREADS + tid] += 1;
    cnt[(p.y * NCLS + t.y) * THREADS + tid] += 1;
    cnt[(p.z * NCLS + t.z) * THREADS + tid] += 1;
    cnt[(p.w * NCLS + t.w) * THREADS + tid] += 1;
}

__global__ __launch_bounds__(THREADS, 3)
void dice_fused_kernel(const int4* __restrict__ yp,
                       const int4* __restrict__ yt,
                       int vecs_per_batch, int chunk,
                       float* __restrict__ out)
{
    __shared__ unsigned char cnt[CNT_BYTES];     // [NKEY][THREADS] u8
    const int tid = threadIdx.x;

    // Zero private counters (int4-vectorized).
    int4* smz = (int4*)cnt;
    #pragma unroll
    for (int i = tid; i < CNT_BYTES / 16; i += THREADS)
        smz[i] = make_int4(0, 0, 0, 0);
    __syncthreads();

    const int batch = blockIdx.x / CHUNKS_PER_BATCH;
    const int sub   = blockIdx.x % CHUNKS_PER_BATCH;
    const long base = (long)batch * vecs_per_batch;
    const int start = sub * chunk;
    const int end   = min(start + chunk, vecs_per_batch);

    // Register software pipeline over quads of int4 (4 x 256 stride).
    // 8 "next" loads have no consumer until after the current bumps ->
    // front-batched: 8 LDG.128 in flight per thread during the bump phase.
    int i = start + tid;
    if (i + 3 * THREADS < end) {
        int4 cp0 = yp[base + i];
        int4 cp1 = yp[base + i +     THREADS];
        int4 cp2 = yp[base + i + 2 * THREADS];
        int4 cp3 = yp[base + i + 3 * THREADS];
        int4 ct0 = yt[base + i];
        int4 ct1 = yt[base + i +     THREADS];
        int4 ct2 = yt[base + i + 2 * THREADS];
        int4 ct3 = yt[base + i + 3 * THREADS];
        i += 4 * THREADS;
        for (; i + 3 * THREADS < end; i += 4 * THREADS) {
            int4 np0 = yp[base + i];
            int4 np1 = yp[base + i +     THREADS];
            int4 np2 = yp[base + i + 2 * THREADS];
            int4 np3 = yp[base + i + 3 * THREADS];
            int4 nt0 = yt[base + i];
            int4 nt1 = yt[base + i +     THREADS];
            int4 nt2 = yt[base + i + 2 * THREADS];
            int4 nt3 = yt[base + i + 3 * THREADS];
            bump(cnt, cp0, ct0, tid);
            bump(cnt, cp1, ct1, tid);
            bump(cnt, cp2, ct2, tid);
            bump(cnt, cp3, ct3, tid);
            cp0 = np0; cp1 = np1; cp2 = np2; cp3 = np3;
            ct0 = nt0; ct1 = nt1; ct2 = nt2; ct3 = nt3;
        }
        bump(cnt, cp0, ct0, tid);
        bump(cnt, cp1, ct1, tid);
        bump(cnt, cp2, ct2, tid);
        bump(cnt, cp3, ct3, tid);
    }
    for (; i < end; i += THREADS) {          // remainder
        int4 p = yp[base + i];
        int4 t = yt[base + i];
        bump(cnt, p, t, tid);
    }
    __syncthreads();

    // Reduce 256 u8 per key via dp4a: key -> 64 u32 words, 2 words/lane.
    const unsigned int* cnt32 = (const unsigned int*)cnt;
    const int wid = tid >> 5, lane = tid & 31;
    for (int k = wid; k < NKEY; k += THREADS / 32) {
        unsigned int s = 0;
        #pragma unroll
        for (int j = 0; j < 2; j++)
            s = __dp4a(cnt32[k * (THREADS / 4) + j * 32 + lane], 0x01010101u, s);
        #pragma unroll
        for (int o = 16; o; o >>= 1)
            s += __shfl_down_sync(0xFFFFFFFFu, s, o);
        if (lane == 0)
            atomicAdd(&g_joint[batch * NKEY + k], s);   // integer: order-independent
    }

    // Last-block ticket.
    __threadfence();
    __shared__ bool is_last;
    if (tid == 0)
        is_last = (atomicAdd(&g_done, 1u) == NBLK - 1);
    __syncthreads();
    if (!is_last) return;
    __threadfence();

    // ---- Finalize from g_joint (L2-hot). All phases STRIDED over their
    // work counts so any THREADS works. ----
    __shared__ unsigned int J[NBATCH * NKEY];
    __shared__ float ctv[NBATCH * NCLS];
    __shared__ float terms[NBATCH * (NCLS - 1)];

    for (int x = tid; x < NBATCH * NKEY; x += THREADS)
        J[x] = g_joint[x];
    __syncthreads();

    // Reset state for next graph replay (after snapshot).
    for (int x = tid; x < NBATCH * NKEY; x += THREADS)
        g_joint[x] = 0u;
    if (tid == 0) g_done = 0u;

    // c_true marginal: ct[b][c] = sum_p J[b][p][c]
    for (int x = tid; x < NBATCH * NCLS; x += THREADS) {
        int b = x / NCLS, c = x % NCLS;
        unsigned int ct = 0;
        #pragma unroll
        for (int p = 0; p < NCLS; p++)
            ct += J[b * NKEY + p * NCLS + c];
        ctv[x] = (float)ct;
    }
    __syncthreads();

    for (int x = tid; x < NBATCH * (NCLS - 1); x += THREADS) {
        int b = x / (NCLS - 1);
        int c = 1 + x % (NCLS - 1);
        unsigned int cp = 0;
        #pragma unroll
        for (int t = 0; t < NCLS; t++)
            cp += J[b * NKEY + c * NCLS + t];
        float ct    = ctv[b * NCLS + c];
        float inter = (float)J[b * NKEY + c * NCLS + c];
        float denom = (float)cp + ct;
        float sumct = 0.0f;
        #pragma unroll
        for (int cc = 1; cc < NCLS; cc++)
            sumct += ctv[b * NCLS + cc];
        float term = 0.0f;
        if (denom > 0.0f)
            term = (ct / sumct * (1.0f / NBATCH)) * (2.0f * inter / denom);
        terms[x] = term;
    }
    __syncthreads();

    if (tid == 0) {
        float tot = 0.0f;
        for (int i2 = 0; i2 < NBATCH * (NCLS - 1); i2++)
            tot += terms[i2];
        out[0] = 1.0f - tot;
    }
}

extern "C" void kernel_launch(void* const* d_in, const int* in_sizes, int n_in,
                              void* d_out, int out_size)
{
    const int4* yp = (const int4*)d_in[0];
    const int4* yt = (const int4*)d_in[1];
    float* out = (float*)d_out;

    int vecs_per_batch = in_sizes[0] / (NBATCH * 4);
    int chunk = (vecs_per_batch + CHUNKS_PER_BATCH - 1) / CHUNKS_PER_BATCH;

    dice_fused_kernel<<<NBLK, THREADS>>>(yp, yt, vecs_per_batch, chunk, out);
    (void)n_in; (void)out_size;
}

// round 9
// speedup vs baseline: 1.0531x; 1.0531x over previous
#include <cuda_runtime.h>
#include <stdint.h>

// DiceFromLabelsLoss: joint-histogram, single fused persistent kernel.
// cp.async.bulk (TMA bulk engine) -> 4-stage x 32KB smem staging, mbarrier
// paced: 96-128KB of global traffic in flight per SM regardless of ptxas
// scheduling (R4-R8 showed ptxas caps LDG MLP at ~2 from C++). Consumers
// read staged int4 pairs from smem and bump private u8 counters
// [NKEY][512] (conflict-free). dp4a epilogue -> integer atomicAdd into
// global joint histogram (exact). Last block finalizes + resets.

#define NBATCH  4
#define NCLS    10
#define NKEY    (NCLS * NCLS)                 // 100
#define THREADS 512
#define CHUNKS_PER_BATCH 37
#define NBLK    (NBATCH * CHUNKS_PER_BATCH)   // 148 = 1 block per SM
#define STAGE_VECS 1024                       // int4 per tensor per stage (16KB)
#define NBUF    4

#define CNT_BYTES   (NKEY * THREADS)              // 51200
#define BUF_BYTES   (2 * STAGE_VECS * 16)         // 32768 per buffer
#define OFF_BUF     CNT_BYTES                     // staging base
#define OFF_MBAR    (CNT_BYTES + NBUF * BUF_BYTES)    // 182272
#define SMEM_BYTES  (OFF_MBAR + 64)

__device__ unsigned int g_joint[NBATCH * NKEY];  // zero-init; reset by last block
__device__ unsigned int g_done;                  // ticket; reset by last block

__device__ __forceinline__ uint32_t smem_u32(const void* p) {
    uint32_t a;
    asm("{ .reg .u64 t; cvta.to.shared.u64 t, %1; cvt.u32.u64 %0, t; }"
        : "=r"(a) : "l"(p));
    return a;
}
__device__ __forceinline__ void mbar_init(uint32_t a, uint32_t cnt) {
    asm volatile("mbarrier.init.shared::cta.b64 [%0], %1;" :: "r"(a), "r"(cnt) : "memory");
}
__device__ __forceinline__ void mbar_expect(uint32_t a, uint32_t bytes) {
    asm volatile("mbarrier.arrive.expect_tx.shared::cta.b64 _, [%0], %1;"
                 :: "r"(a), "r"(bytes) : "memory");
}
__device__ __forceinline__ void bulk_g2s(uint32_t dst, const void* src,
                                         uint32_t bytes, uint32_t mbar) {
    asm volatile("cp.async.bulk.shared::cta.global.mbarrier::complete_tx::bytes "
                 "[%0], [%1], %2, [%3];"
                 :: "r"(dst), "l"(src), "r"(bytes), "r"(mbar) : "memory");
}
__device__ __forceinline__ void mbar_wait(uint32_t a, uint32_t parity) {
    asm volatile(
        "{\n\t"
        ".reg .pred P;\n\t"
        "W_%=:\n\t"
        "mbarrier.try_wait.parity.acquire.cta.shared::cta.b64 P, [%0], %1, 0x989680;\n\t"
        "@P bra.uni D_%=;\n\t"
        "bra.uni W_%=;\n\t"
        "D_%=:\n\t"
        "}" :: "r"(a), "r"(parity) : "memory");
}

__device__ __forceinline__ void bump(unsigned char* cnt, int4 p, int4 t, int tid)
{
    cnt[(p.x * NCLS + t.x) * THREADS + tid] += 1;
    cnt[(p.y * NCLS + t.y) * THREADS + tid] += 1;
    cnt[(p.z * NCLS + t.z) * THREADS + tid] += 1;
    cnt[(p.w * NCLS + t.w) * THREADS + tid] += 1;
}

__global__ __launch_bounds__(THREADS, 1)
void dice_fused_kernel(const int4* __restrict__ yp,
                       const int4* __restrict__ yt,
                       int vecs_per_batch, int chunk,
                       float* __restrict__ out)
{
    extern __shared__ unsigned char smem_raw[];
    unsigned char* cnt = smem_raw;                    // [NKEY][512] u8
    const int tid = threadIdx.x;
    const uint32_t smem_base = smem_u32(smem_raw);
    const uint32_t mbar0 = smem_base + OFF_MBAR;

    // Zero private counters; init mbarriers.
    int4* smz = (int4*)cnt;
    #pragma unroll
    for (int i = tid; i < CNT_BYTES / 16; i += THREADS)
        smz[i] = make_int4(0, 0, 0, 0);
    if (tid == 0) {
        #pragma unroll
        for (int b = 0; b < NBUF; b++)
            mbar_init(mbar0 + b * 8, 1);
    }
    __syncthreads();

    const int batch = blockIdx.x / CHUNKS_PER_BATCH;
    const int sub   = blockIdx.x % CHUNKS_PER_BATCH;
    const long base = (long)batch * vecs_per_batch;
    const int start = sub * chunk;
    const int end   = min(start + chunk, vecs_per_batch);
    const int span  = end - start;
    const int nst   = (span + STAGE_VECS - 1) / STAGE_VECS;

    // Prologue: issue first NBUF stages.
    if (tid == 0) {
        for (int s = 0; s < NBUF && s < nst; s++) {
            int b = s & (NBUF - 1);
            int ns = min(STAGE_VECS, span - s * STAGE_VECS);
            uint32_t bytes = (uint32_t)ns * 16u;
            uint32_t dp = smem_base + OFF_BUF + b * BUF_BYTES;
            uint32_t dt = dp + STAGE_VECS * 16;
            mbar_expect(mbar0 + b * 8, 2u * bytes);
            bulk_g2s(dp, yp + base + start + s * STAGE_VECS, bytes, mbar0 + b * 8);
            bulk_g2s(dt, yt + base + start + s * STAGE_VECS, bytes, mbar0 + b * 8);
        }
    }

    // Steady state: wait(s) -> consume(s) -> sync -> issue(s+NBUF).
    for (int s = 0; s < nst; s++) {
        int b = s & (NBUF - 1);
        mbar_wait(mbar0 + b * 8, (s >> 2) & 1);

        const int4* bp = (const int4*)(smem_raw + OFF_BUF + b * BUF_BYTES);
        const int4* bt = bp + STAGE_VECS;
        int ns = min(STAGE_VECS, span - s * STAGE_VECS);
        for (int j = tid; j < ns; j += THREADS)
            bump(cnt, bp[j], bt[j], tid);

        __syncthreads();   // buffer b fully consumed by all threads

        int f = s + NBUF;
        if (tid == 0 && f < nst) {
            int ns2 = min(STAGE_VECS, span - f * STAGE_VECS);
            uint32_t bytes = (uint32_t)ns2 * 16u;
            uint32_t dp = smem_base + OFF_BUF + b * BUF_BYTES;
            uint32_t dt = dp + STAGE_VECS * 16;
            mbar_expect(mbar0 + b * 8, 2u * bytes);
            bulk_g2s(dp, yp + base + start + f * STAGE_VECS, bytes, mbar0 + b * 8);
            bulk_g2s(dt, yt + base + start + f * STAGE_VECS, bytes, mbar0 + b * 8);
        }
    }
    __syncthreads();

    // Reduce 512 u8 per key via dp4a: key -> 128 u32 words, 4 words/lane.
    const unsigned int* cnt32 = (const unsigned int*)cnt;
    const int wid = tid >> 5, lane = tid & 31;
    for (int k = wid; k < NKEY; k += THREADS / 32) {
        unsigned int s = 0;
        #pragma unroll
        for (int j = 0; j < 4; j++)
            s = __dp4a(cnt32[k * (THREADS / 4) + j * 32 + lane], 0x01010101u, s);
        #pragma unroll
        for (int o = 16; o; o >>= 1)
            s += __shfl_down_sync(0xFFFFFFFFu, s, o);
        if (lane == 0)
            atomicAdd(&g_joint[batch * NKEY + k], s);   // integer: order-independent
    }

    // Last-block ticket.
    __threadfence();
    __shared__ bool is_last;
    if (tid == 0)
        is_last = (atomicAdd(&g_done, 1u) == NBLK - 1);
    __syncthreads();
    if (!is_last) return;
    __threadfence();

    // ---- Finalize from g_joint (L2-hot). Strided phases. ----
    __shared__ unsigned int J[NBATCH * NKEY];
    __shared__ float ctv[NBATCH * NCLS];
    __shared__ float terms[NBATCH * (NCLS - 1)];

    for (int x = tid; x < NBATCH * NKEY; x += THREADS)
        J[x] = g_joint[x];
    __syncthreads();

    for (int x = tid; x < NBATCH * NKEY; x += THREADS)
        g_joint[x] = 0u;
    if (tid == 0) g_done = 0u;

    for (int x = tid; x < NBATCH * NCLS; x += THREADS) {
        int b = x / NCLS, c = x % NCLS;
        unsigned int ct = 0;
        #pragma unroll
        for (int p = 0; p < NCLS; p++)
            ct += J[b * NKEY + p * NCLS + c];
        ctv[x] = (float)ct;
    }
    __syncthreads();

    for (int x = tid; x < NBATCH * (NCLS - 1); x += THREADS) {
        int b = x / (NCLS - 1);
        int c = 1 + x % (NCLS - 1);
        unsigned int cp = 0;
        #pragma unroll
        for (int t = 0; t < NCLS; t++)
            cp += J[b * NKEY + c * NCLS + t];
        float ct    = ctv[b * NCLS + c];
        float inter = (float)J[b * NKEY + c * NCLS + c];
        float denom = (float)cp + ct;
        float sumct = 0.0f;
        #pragma unroll
        for (int cc = 1; cc < NCLS; cc++)
            sumct += ctv[b * NCLS + cc];
        float term = 0.0f;
        if (denom > 0.0f)
            term = (ct / sumct * (1.0f / NBATCH)) * (2.0f * inter / denom);
        terms[x] = term;
    }
    __syncthreads();

    if (tid == 0) {
        float tot = 0.0f;
        for (int i2 = 0; i2 < NBATCH * (NCLS - 1); i2++)
            tot += terms[i2];
        out[0] = 1.0f - tot;
    }
}

extern "C" void kernel_launch(void* const* d_in, const int* in_sizes, int n_in,
                              void* d_out, int out_size)
{
    const int4* yp = (const int4*)d_in[0];
    const int4* yt = (const int4*)d_in[1];
    float* out = (float*)d_out;

    int vecs_per_batch = in_sizes[0] / (NBATCH * 4);
    int chunk = (vecs_per_batch + CHUNKS_PER_BATCH - 1) / CHUNKS_PER_BATCH;

    cudaFuncSetAttribute(dice_fused_kernel,
                         cudaFuncAttributeMaxDynamicSharedMemorySize, SMEM_BYTES);

    dice_fused_kernel<<<NBLK, THREADS, SMEM_BYTES>>>(yp, yt, vecs_per_batch,
                                                     chunk, out);
    (void)n_in; (void)out_size;
}

// round 11
// speedup vs baseline: 1.1561x; 1.0978x over previous
#include <cuda_runtime.h>
#include <stdint.h>

// DiceFromLabelsLoss: joint-histogram, single fused persistent kernel.
// cp.async.bulk 4-stage x 32KB smem staging (guaranteed MLP) + PROVABLY
// conflict-free u8 counter layout: byte A(k,tid) =
// ((k>>2)*16 + wid)*128 + lane*4 + (k&3)  -> word bank == lane for ANY
// key pattern (R9's [key][512] layout had 4-way conflicts: bank was
// (tid/4)%32, key-independent, costing 27.6K crossbar cyc/SM).
// Integer atomicAdd joint histogram (exact); last block finalizes+resets.

#define NBATCH  4
#define NCLS    10
#define NKEY    (NCLS * NCLS)                 // 100
#define THREADS 512
#define CHUNKS_PER_BATCH 37
#define NBLK    (NBATCH * CHUNKS_PER_BATCH)   // 148 = 1 block per SM
#define STAGE_VECS 1024                       // int4 per tensor per stage (16KB)
#define NBUF    4

#define CNT_BYTES   (25 * 16 * 128)               // 51200 (q=25, wid=16, 128B rows)
#define BUF_BYTES   (2 * STAGE_VECS * 16)         // 32768 per buffer
#define OFF_BUF     CNT_BYTES
#define OFF_MBAR    (CNT_BYTES + NBUF * BUF_BYTES)    // 182272
#define SMEM_BYTES  (OFF_MBAR + 64)

__device__ unsigned int g_joint[NBATCH * NKEY];  // zero-init; reset by last block
__device__ unsigned int g_done;                  // ticket; reset by last block

__device__ __forceinline__ uint32_t smem_u32(const void* p) {
    uint32_t a;
    asm("{ .reg .u64 t; cvta.to.shared.u64 t, %1; cvt.u32.u64 %0, t; }"
        : "=r"(a) : "l"(p));
    return a;
}
__device__ __forceinline__ void mbar_init(uint32_t a, uint32_t cnt) {
    asm volatile("mbarrier.init.shared::cta.b64 [%0], %1;" :: "r"(a), "r"(cnt) : "memory");
}
__device__ __forceinline__ void mbar_expect(uint32_t a, uint32_t bytes) {
    asm volatile("mbarrier.arrive.expect_tx.shared::cta.b64 _, [%0], %1;"
                 :: "r"(a), "r"(bytes) : "memory");
}
__device__ __forceinline__ void bulk_g2s(uint32_t dst, const void* src,
                                         uint32_t bytes, uint32_t mbar) {
    asm volatile("cp.async.bulk.shared::cta.global.mbarrier::complete_tx::bytes "
                 "[%0], [%1], %2, [%3];"
                 :: "r"(dst), "l"(src), "r"(bytes), "r"(mbar) : "memory");
}
__device__ __forceinline__ void mbar_wait(uint32_t a, uint32_t parity) {
    asm volatile(
        "{\n\t"
        ".reg .pred P;\n\t"
        "W_%=:\n\t"
        "mbarrier.try_wait.parity.acquire.cta.shared::cta.b64 P, [%0], %1, 0x989680;\n\t"
        "@P bra.uni D_%=;\n\t"
        "bra.uni W_%=;\n\t"
        "D_%=:\n\t"
        "}" :: "r"(a), "r"(parity) : "memory");
}

// Conflict-free u8 bump: base = cnt + wid*128 + lane*4 (per-thread const).
// Offset(k) = ((k & ~3) << 9) + (k & 3):  word bank == lane for all k.
__device__ __forceinline__ void bump1(unsigned char* base, int p, int t) {
    int k = p * NCLS + t;
    base[((k & ~3) << 9) + (k & 3)] += 1;
}
__device__ __forceinline__ void bump(unsigned char* base, int4 p, int4 t) {
    bump1(base, p.x, t.x);
    bump1(base, p.y, t.y);
    bump1(base, p.z, t.z);
    bump1(base, p.w, t.w);
}

__global__ __launch_bounds__(THREADS, 1)
void dice_fused_kernel(const int4* __restrict__ yp,
                       const int4* __restrict__ yt,
                       int vecs_per_batch, int chunk,
                       float* __restrict__ out)
{
    extern __shared__ unsigned char smem_raw[];
    unsigned char* cnt = smem_raw;
    const int tid = threadIdx.x;
    const int wid = tid >> 5, lane = tid & 31;
    unsigned char* mybase = cnt + wid * 128 + lane * 4;
    const uint32_t smem_base = smem_u32(smem_raw);
    const uint32_t mbar0 = smem_base + OFF_MBAR;

    // Zero counters; init mbarriers.
    int4* smz = (int4*)cnt;
    #pragma unroll
    for (int i = tid; i < CNT_BYTES / 16; i += THREADS)
        smz[i] = make_int4(0, 0, 0, 0);
    if (tid == 0) {
        #pragma unroll
        for (int b = 0; b < NBUF; b++)
            mbar_init(mbar0 + b * 8, 1);
    }
    __syncthreads();

    const int batch = blockIdx.x / CHUNKS_PER_BATCH;
    const int sub   = blockIdx.x % CHUNKS_PER_BATCH;
    const long base = (long)batch * vecs_per_batch;
    const int start = sub * chunk;
    const int end   = min(start + chunk, vecs_per_batch);
    const int span  = end - start;
    const int nst   = (span + STAGE_VECS - 1) / STAGE_VECS;

    // Prologue: issue first NBUF stages.
    if (tid == 0) {
        for (int s = 0; s < NBUF && s < nst; s++) {
            int b = s & (NBUF - 1);
            int ns = min(STAGE_VECS, span - s * STAGE_VECS);
            uint32_t bytes = (uint32_t)ns * 16u;
            uint32_t dp = smem_base + OFF_BUF + b * BUF_BYTES;
            uint32_t dt = dp + STAGE_VECS * 16;
            mbar_expect(mbar0 + b * 8, 2u * bytes);
            bulk_g2s(dp, yp + base + start + s * STAGE_VECS, bytes, mbar0 + b * 8);
            bulk_g2s(dt, yt + base + start + s * STAGE_VECS, bytes, mbar0 + b * 8);
        }
    }

    // Steady state: wait(s) -> consume(s) -> sync -> issue(s+NBUF).
    for (int s = 0; s < nst; s++) {
        int b = s & (NBUF - 1);
        mbar_wait(mbar0 + b * 8, (s >> 2) & 1);

        const int4* bp = (const int4*)(smem_raw + OFF_BUF + b * BUF_BYTES);
        const int4* bt = bp + STAGE_VECS;
        int ns = min(STAGE_VECS, span - s * STAGE_VECS);
        for (int j = tid; j < ns; j += THREADS)
            bump(mybase, bp[j], bt[j]);

        __syncthreads();   // buffer b fully consumed by all threads

        int f = s + NBUF;
        if (tid == 0 && f < nst) {
            int ns2 = min(STAGE_VECS, span - f * STAGE_VECS);
            uint32_t bytes = (uint32_t)ns2 * 16u;
            uint32_t dp = smem_base + OFF_BUF + b * BUF_BYTES;
            uint32_t dt = dp + STAGE_VECS * 16;
            mbar_expect(mbar0 + b * 8, 2u * bytes);
            bulk_g2s(dp, yp + base + start + f * STAGE_VECS, bytes, mbar0 + b * 8);
            bulk_g2s(dt, yt + base + start + f * STAGE_VECS, bytes, mbar0 + b * 8);
        }
    }
    __syncthreads();

    // Epilogue: warp w sums keys k = w, w+16, ... Count(k, thread(w2,l)) is
    // byte (k&3) of word ((k>>2)*16 + w2)*32 + l  -> lane-indexed, no conflicts.
    const unsigned int* cnt32 = (const unsigned int*)cnt;
    for (int k = wid; k < NKEY; k += THREADS / 32) {
        int q = k >> 2, r = (k & 3) * 8;
        unsigned int s = 0;
        #pragma unroll
        for (int j = 0; j < 16; j++)
            s += (cnt32[(q * 16 + j) * 32 + lane] >> r) & 0xFFu;
        #pragma unroll
        for (int o = 16; o; o >>= 1)
            s += __shfl_down_sync(0xFFFFFFFFu, s, o);
        if (lane == 0)
            atomicAdd(&g_joint[batch * NKEY + k], s);   // integer: order-independent
    }

    // Last-block ticket.
    __threadfence();
    __shared__ bool is_last;
    if (tid == 0)
        is_last = (atomicAdd(&g_done, 1u) == NBLK - 1);
    __syncthreads();
    if (!is_last) return;
    __threadfence();

    // ---- Finalize from g_joint (L2-hot). Strided phases. ----
    __shared__ unsigned int J[NBATCH * NKEY];
    __shared__ float ctv[NBATCH * NCLS];
    __shared__ float terms[NBATCH * (NCLS - 1)];

    for (int x = tid; x < NBATCH * NKEY; x += THREADS)
        J[x] = g_joint[x];
    __syncthreads();

    for (int x = tid; x < NBATCH * NKEY; x += THREADS)
        g_joint[x] = 0u;
    if (tid == 0) g_done = 0u;

    for (int x = tid; x < NBATCH * NCLS; x += THREADS) {
        int b = x / NCLS, c = x % NCLS;
        unsigned int ct = 0;
        #pragma unroll
        for (int p = 0; p < NCLS; p++)
            ct += J[b * NKEY + p * NCLS + c];
        ctv[x] = (float)ct;
    }
    __syncthreads();

    for (int x = tid; x < NBATCH * (NCLS - 1); x += THREADS) {
        int b = x / (NCLS - 1);
        int c = 1 + x % (NCLS - 1);
        unsigned int cp = 0;
        #pragma unroll
        for (int t = 0; t < NCLS; t++)
            cp += J[b * NKEY + c * NCLS + t];
        float ct    = ctv[b * NCLS + c];
        float inter = (float)J[b * NKEY + c * NCLS + c];
        float denom = (float)cp + ct;
        float sumct = 0.0f;
        #pragma unroll
        for (int cc = 1; cc < NCLS; cc++)
            sumct += ctv[b * NCLS + cc];
        float term = 0.0f;
        if (denom > 0.0f)
            term = (ct / sumct * (1.0f / NBATCH)) * (2.0f * inter / denom);
        terms[x] = term;
    }
    __syncthreads();

    if (tid == 0) {
        float tot = 0.0f;
        for (int i2 = 0; i2 < NBATCH * (NCLS - 1); i2++)
            tot += terms[i2];
        out[0] = 1.0f - tot;
    }
}

extern "C" void kernel_launch(void* const* d_in, const int* in_sizes, int n_in,
                              void* d_out, int out_size)
{
    const int4* yp = (const int4*)d_in[0];
    const int4* yt = (const int4*)d_in[1];
    float* out = (float*)d_out;

    int vecs_per_batch = in_sizes[0] / (NBATCH * 4);
    int chunk = (vecs_per_batch + CHUNKS_PER_BATCH - 1) / CHUNKS_PER_BATCH;

    cudaFuncSetAttribute(dice_fused_kernel,
                         cudaFuncAttributeMaxDynamicSharedMemorySize, SMEM_BYTES);

    dice_fused_kernel<<<NBLK, THREADS, SMEM_BYTES>>>(yp, yt, vecs_per_batch,
                                                     chunk, out);
    (void)n_in; (void)out_size;
}